// round 1
// baseline (speedup 1.0000x reference)
#include <cuda_runtime.h>

#define S 1024
#define D 64
#define NPOS 64
#define BH 48
#define KC 128
#define TQ 32
#define NPOS_M1 63.0f

// Scratch (allowed: __device__ globals, no runtime allocation)
__device__ float g_keypT[(size_t)BH * D * S];    // [bh][d][s]  (transposed key projection)
__device__ float g_lint [(size_t)BH * S * NPOS]; // [bh][s][p]  (logits_int)

// ---------------------------------------------------------------------------
// Kernel A1: g_keypT[bh][d][s] = sum_k key[bh][s][k] * w_k[k][d]
// Block: (bh, s-chunk of 64), 256 threads, 4x4 register micro-tiles.
// ---------------------------------------------------------------------------
__global__ __launch_bounds__(256) void keyproj_kernel(
    const float* __restrict__ key, const float* __restrict__ wk)
{
    __shared__ float wk_s[64 * 64];   // [k][d]
    __shared__ float in_s[64 * 68];   // [s_local][k], padded
    const int bh  = blockIdx.x;
    const int s0  = blockIdx.y * 64;
    const int tid = threadIdx.x;

    for (int idx = tid; idx < 1024; idx += 256)
        ((float4*)wk_s)[idx] = ((const float4*)wk)[idx];
    {
        const float* kp = key + ((size_t)bh * S + s0) * D;
        for (int idx = tid; idx < 64 * 16; idx += 256) {
            int r = idx >> 4, c = idx & 15;
            float4 v = ((const float4*)(kp + (size_t)r * D))[c];
            *(float4*)&in_s[r * 68 + c * 4] = v;
        }
    }
    __syncthreads();

    // dy in low bits -> conflict-free wk_s reads; sx warp-quasi-uniform -> cheap in_s reads
    const int dy = tid & 15;   // d-group: d = 4*dy..4*dy+3
    const int sx = tid >> 4;   // s-group: s_local = 4*sx..4*sx+3

    float acc[4][4];
#pragma unroll
    for (int i = 0; i < 4; i++)
#pragma unroll
        for (int j = 0; j < 4; j++) acc[i][j] = 0.f;

#pragma unroll
    for (int k4 = 0; k4 < 16; k4++) {
        float4 av[4];
#pragma unroll
        for (int i = 0; i < 4; i++)
            av[i] = *(const float4*)&in_s[(4 * sx + i) * 68 + 4 * k4];
#pragma unroll
        for (int t = 0; t < 4; t++) {
            float4 wv = *(const float4*)&wk_s[(4 * k4 + t) * 64 + 4 * dy];
#pragma unroll
            for (int i = 0; i < 4; i++) {
                float a = (t == 0) ? av[i].x : (t == 1) ? av[i].y : (t == 2) ? av[i].z : av[i].w;
                acc[i][0] += a * wv.x; acc[i][1] += a * wv.y;
                acc[i][2] += a * wv.z; acc[i][3] += a * wv.w;
            }
        }
    }
#pragma unroll
    for (int j = 0; j < 4; j++) {
        float4 o = make_float4(acc[0][j], acc[1][j], acc[2][j], acc[3][j]);
        *(float4*)&g_keypT[((size_t)bh * D + 4 * dy + j) * S + s0 + 4 * sx] = o;
    }
}

// ---------------------------------------------------------------------------
// Kernel A2: g_lint[bh][s][p] = sum_d qk[bh][s][d] * pos_emb[d][p]
// qk = query if is_cope_k else key.
// ---------------------------------------------------------------------------
__global__ __launch_bounds__(256) void lint_kernel(
    const float* __restrict__ query, const float* __restrict__ key,
    const float* __restrict__ pe, const int* __restrict__ flag)
{
    __shared__ float pe_s[64 * 64];   // [d][p]
    __shared__ float in_s[64 * 68];   // [s_local][d], padded
    const int bh  = blockIdx.x;
    const int s0  = blockIdx.y * 64;
    const int tid = threadIdx.x;

    const float* src = (flag[0] != 0) ? query : key;

    for (int idx = tid; idx < 1024; idx += 256)
        ((float4*)pe_s)[idx] = ((const float4*)pe)[idx];
    {
        const float* sp = src + ((size_t)bh * S + s0) * D;
        for (int idx = tid; idx < 64 * 16; idx += 256) {
            int r = idx >> 4, c = idx & 15;
            float4 v = ((const float4*)(sp + (size_t)r * D))[c];
            *(float4*)&in_s[r * 68 + c * 4] = v;
        }
    }
    __syncthreads();

    const int px = tid & 15;   // p-group (low bits -> coalesced writes)
    const int sy = tid >> 4;   // s-group

    float acc[4][4];
#pragma unroll
    for (int i = 0; i < 4; i++)
#pragma unroll
        for (int j = 0; j < 4; j++) acc[i][j] = 0.f;

#pragma unroll
    for (int k4 = 0; k4 < 16; k4++) {
        float4 av[4];
#pragma unroll
        for (int i = 0; i < 4; i++)
            av[i] = *(const float4*)&in_s[(4 * sy + i) * 68 + 4 * k4];
#pragma unroll
        for (int t = 0; t < 4; t++) {
            float4 wv = *(const float4*)&pe_s[(4 * k4 + t) * 64 + 4 * px];
#pragma unroll
            for (int i = 0; i < 4; i++) {
                float a = (t == 0) ? av[i].x : (t == 1) ? av[i].y : (t == 2) ? av[i].z : av[i].w;
                acc[i][0] += a * wv.x; acc[i][1] += a * wv.y;
                acc[i][2] += a * wv.z; acc[i][3] += a * wv.w;
            }
        }
    }
#pragma unroll
    for (int i = 0; i < 4; i++) {
        float4 o = make_float4(acc[i][0], acc[i][1], acc[i][2], acc[i][3]);
        *(float4*)&g_lint[((size_t)bh * S + s0 + 4 * sy + i) * NPOS + 4 * px] = o;
    }
}

// ---------------------------------------------------------------------------
// Kernel B: per (bh, 32-row q-tile). Backward chunked logits -> sigmoid ->
// suffix scan -> clamp/interp. Early bulk-fill once all rows' carries >= 63.
// Dynamic smem layout (floats):
//   qs[32*64] | li[32*64] | kpT[64*128] | gs[32*128] | carry[32] | redv[32]
// ---------------------------------------------------------------------------
#define SMEM_B_FLOATS (2048 + 2048 + 8192 + 4096 + 32 + 32)
#define SMEM_B_BYTES  (SMEM_B_FLOATS * 4)

__global__ __launch_bounds__(256) void cope_kernel(
    const float* __restrict__ query, float* __restrict__ out)
{
    extern __shared__ float sm[];
    float* qs    = sm;                       // scaled query tile [32][64]
    float* li    = sm + 2048;                // logits_int tile   [32][64]
    float* kpT   = sm + 4096;                // keyp chunk        [64][128] (d-major)
    float* gs    = sm + 4096 + 8192;         // gates chunk       [32][128]
    float* carry = gs + 4096;                // [32]
    float* redv  = carry + 32;               // [1] used

    const int bh   = blockIdx.y;
    const int q0   = blockIdx.x * TQ;
    const int tid  = threadIdx.x;
    const int lane = tid & 31;
    const int wrp  = tid >> 5;

    // Load scaled Q tile + logits_int tile
    for (int idx = tid; idx < TQ * 16; idx += 256) {
        int r = idx >> 4, c = idx & 15;
        float4 v = ((const float4*)(query + ((size_t)bh * S + q0 + r) * D))[c];
        v.x *= 0.125f; v.y *= 0.125f; v.z *= 0.125f; v.w *= 0.125f;
        *(float4*)&qs[r * D + c * 4] = v;
        float4 L = ((const float4*)(g_lint + ((size_t)bh * S + q0 + r) * NPOS))[c];
        *(float4*)&li[r * NPOS + c * 4] = L;
    }
    if (tid < TQ) carry[tid] = 0.f;
    __syncthreads();

    const int cx = tid & 31;   // col-group: cols 4*cx..4*cx+3 (warp-contiguous)
    const int cy = tid >> 5;   // row-group: rows 4*cy..4*cy+3 (warp-uniform)

    for (int jc = S - KC; jc >= 0; jc -= KC) {
        // Load keypT chunk [64][128] (already d-major in gmem -> no transpose)
        for (int idx = tid; idx < D * (KC / 4); idx += 256) {
            int d = idx >> 5, c4 = idx & 31;
            float4 v = ((const float4*)(g_keypT + ((size_t)bh * D + d) * S + jc))[c4];
            *(float4*)&kpT[d * KC + c4 * 4] = v;
        }
        __syncthreads();

        // 32x128x64 fp32 GEMM tile, 4x4 per thread
        float acc[4][4];
#pragma unroll
        for (int i = 0; i < 4; i++)
#pragma unroll
            for (int j = 0; j < 4; j++) acc[i][j] = 0.f;

#pragma unroll
        for (int d4 = 0; d4 < 16; d4++) {
            float4 qv[4];
#pragma unroll
            for (int i = 0; i < 4; i++)
                qv[i] = *(const float4*)&qs[(4 * cy + i) * D + 4 * d4];
#pragma unroll
            for (int t = 0; t < 4; t++) {
                float4 kv = *(const float4*)&kpT[(4 * d4 + t) * KC + 4 * cx];
#pragma unroll
                for (int i = 0; i < 4; i++) {
                    float a = (t == 0) ? qv[i].x : (t == 1) ? qv[i].y : (t == 2) ? qv[i].z : qv[i].w;
                    acc[i][0] += a * kv.x; acc[i][1] += a * kv.y;
                    acc[i][2] += a * kv.z; acc[i][3] += a * kv.w;
                }
            }
        }

        // sigmoid -> gates smem
#pragma unroll
        for (int i = 0; i < 4; i++) {
            float4 g;
            g.x = 1.f / (1.f + expf(-acc[i][0]));
            g.y = 1.f / (1.f + expf(-acc[i][1]));
            g.z = 1.f / (1.f + expf(-acc[i][2]));
            g.w = 1.f / (1.f + expf(-acc[i][3]));
            *(float4*)&gs[(4 * cy + i) * KC + 4 * cx] = g;
        }
        __syncthreads();

        // Suffix scan + interpolated output. Warp w handles rows w, w+8, w+16, w+24.
        for (int rr = 0; rr < 4; rr++) {
            int r = wrp + 8 * rr;
            float c0 = carry[r];
            float* outrow = out + ((size_t)bh * S + q0 + r) * S + jc;
#pragma unroll
            for (int sub = (KC / 32) - 1; sub >= 0; sub--) {
                float v = gs[r * KC + sub * 32 + lane];
#pragma unroll
                for (int off = 1; off < 32; off <<= 1) {
                    float n = __shfl_down_sync(0xffffffffu, v, off);
                    if (lane + off < 32) v += n;
                }
                float pos = c0 + v;                          // suffix sum incl. this col
                c0 = __shfl_sync(0xffffffffu, pos, 0);       // new carry = old + sub total
                pos = fminf(pos, NPOS_M1);
                float pf = floorf(pos);
                int   ip = (int)pf;
                float w  = pos - pf;
                int   ic = (ip < 63) ? ip + 1 : 63;
                float lf = li[r * NPOS + ip];
                float lc = li[r * NPOS + ic];
                outrow[sub * 32 + lane] = lc * w + lf * (1.0f - w);
            }
            if (lane == 0) carry[r] = c0;
        }
        __syncthreads();

        // Block-wide min carry
        if (tid < 32) {
            float m = carry[tid];
#pragma unroll
            for (int off = 16; off; off >>= 1)
                m = fminf(m, __shfl_down_sync(0xffffffffu, m, off));
            if (tid == 0) redv[0] = m;
        }
        __syncthreads();

        if (redv[0] >= NPOS_M1) {
            // All remaining columns [0, jc) clamp to pos=63 -> row-constant fill
            if (jc > 0) {
                int nf4 = jc >> 2;
                for (int r = 0; r < TQ; r++) {
                    float Lv = li[r * NPOS + 63];
                    float4 o = make_float4(Lv, Lv, Lv, Lv);
                    float4* orow = (float4*)(out + ((size_t)bh * S + q0 + r) * S);
                    for (int c4 = tid; c4 < nf4; c4 += 256) orow[c4] = o;
                }
            }
            break;  // uniform across block
        }
    }
}

// ---------------------------------------------------------------------------
extern "C" void kernel_launch(void* const* d_in, const int* in_sizes, int n_in,
                              void* d_out, int out_size) {
    const float* query = (const float*)d_in[0];
    // d_in[1] = attn_logits (unused in mode 1)
    const float* key   = (const float*)d_in[2];
    // d_in[3] = value (unused)
    const float* pe    = (const float*)d_in[4];
    const float* wk    = (const float*)d_in[5];
    const int*   flag  = (const int*)d_in[6];
    float* out = (float*)d_out;

    keyproj_kernel<<<dim3(BH, S / 64), 256>>>(key, wk);
    lint_kernel<<<dim3(BH, S / 64), 256>>>(query, key, pe, flag);

    cudaFuncSetAttribute(cope_kernel,
                         cudaFuncAttributeMaxDynamicSharedMemorySize, SMEM_B_BYTES);
    cope_kernel<<<dim3(S / TQ, BH), 256, SMEM_B_BYTES>>>(query, out);
}

// round 2
// speedup vs baseline: 1.2291x; 1.2291x over previous
#include <cuda_runtime.h>
#include <cstdint>

#define S 1024
#define D 64
#define NPOS 64
#define BH 48
#define KC 128
#define TQ 32
#define KP_COLS 384            // precomputed keyproj tail columns
#define KP_START (S - KP_COLS) // 640
#define NPOS_M1 63.0f

// Scratch (allowed: __device__ globals)
__device__ float g_keypT[(size_t)BH * D * S];    // [bh][d][s] (only s >= KP_START filled)
__device__ float g_lint [(size_t)BH * S * NPOS]; // [bh][s][p]

// ---- packed f32x2 helpers (FFMA2) -----------------------------------------
__device__ __forceinline__ unsigned long long pack2(float a) {
    unsigned long long r;
    asm("mov.b64 %0, {%1, %1};" : "=l"(r) : "f"(a));
    return r;
}
__device__ __forceinline__ void fma2(unsigned long long& d,
                                     unsigned long long a, unsigned long long b) {
    asm("fma.rn.f32x2 %0, %1, %2, %0;" : "+l"(d) : "l"(a), "l"(b));
}
__device__ __forceinline__ float2 unpack2(unsigned long long v) {
    float2 f;
    asm("mov.b64 {%0, %1}, %2;" : "=f"(f.x), "=f"(f.y) : "l"(v));
    return f;
}

// ---------------------------------------------------------------------------
// Fused precompute: role<16 -> lint (all s), role>=16 -> keyproj (last 384 s)
// ---------------------------------------------------------------------------
__global__ __launch_bounds__(256) void precompute_kernel(
    const float* __restrict__ query, const float* __restrict__ key,
    const float* __restrict__ pe, const float* __restrict__ wk,
    const int* __restrict__ flag)
{
    __shared__ float w_s[64 * 64];    // weights: pe [d][p] or wk [k][d]
    __shared__ float in_s[64 * 68];   // input rows [s_local][contract]
    const int bh   = blockIdx.x;
    const int role = blockIdx.y;
    const int tid  = threadIdx.x;
    const bool is_lint = (role < 16);
    const int s0 = is_lint ? role * 64 : KP_START + (role - 16) * 64;

    const float* wsrc = is_lint ? pe : wk;
    const float* isrc = is_lint ? ((flag[0] != 0) ? query : key) : key;

    for (int idx = tid; idx < 1024; idx += 256)
        ((float4*)w_s)[idx] = ((const float4*)wsrc)[idx];
    {
        const float* p = isrc + ((size_t)bh * S + s0) * D;
        for (int idx = tid; idx < 64 * 16; idx += 256) {
            int r = idx >> 4, c = idx & 15;
            float4 v = ((const float4*)(p + (size_t)r * D))[c];
            *(float4*)&in_s[r * 68 + c * 4] = v;
        }
    }
    __syncthreads();

    const int ox = tid & 15;   // output-minor group (p for lint, d for keyproj)
    const int sy = tid >> 4;   // s-row group

    unsigned long long acc[4][2];
#pragma unroll
    for (int i = 0; i < 4; i++) { acc[i][0] = 0ull; acc[i][1] = 0ull; }

#pragma unroll
    for (int k4 = 0; k4 < 16; k4++) {
        float4 av[4];
#pragma unroll
        for (int i = 0; i < 4; i++)
            av[i] = *(const float4*)&in_s[(4 * sy + i) * 68 + 4 * k4];
#pragma unroll
        for (int t = 0; t < 4; t++) {
            ulonglong2 wv = *(const ulonglong2*)&w_s[(4 * k4 + t) * 64 + 4 * ox];
#pragma unroll
            for (int i = 0; i < 4; i++) {
                float a = (t == 0) ? av[i].x : (t == 1) ? av[i].y : (t == 2) ? av[i].z : av[i].w;
                unsigned long long a2 = pack2(a);
                fma2(acc[i][0], a2, wv.x);
                fma2(acc[i][1], a2, wv.y);
            }
        }
    }

    float a_[4][4];
#pragma unroll
    for (int i = 0; i < 4; i++) {
        float2 u0 = unpack2(acc[i][0]), u1 = unpack2(acc[i][1]);
        a_[i][0] = u0.x; a_[i][1] = u0.y; a_[i][2] = u1.x; a_[i][3] = u1.y;
    }

    if (is_lint) {
#pragma unroll
        for (int i = 0; i < 4; i++) {
            float4 o = make_float4(a_[i][0], a_[i][1], a_[i][2], a_[i][3]);
            *(float4*)&g_lint[((size_t)bh * S + s0 + 4 * sy + i) * NPOS + 4 * ox] = o;
        }
    } else {
#pragma unroll
        for (int j = 0; j < 4; j++) {
            float4 o = make_float4(a_[0][j], a_[1][j], a_[2][j], a_[3][j]);
            *(float4*)&g_keypT[((size_t)bh * D + 4 * ox + j) * S + s0 + 4 * sy] = o;
        }
    }
}

// ---------------------------------------------------------------------------
// Main kernel: per (bh, 32-row q tile). Backward chunks, register scan,
// early bulk-fill. Fallback on-the-fly keyproj for jc < KP_START (rare/never).
// smem: qs[32*64] | li[32*64] | kpT[64*128] | carry[32] | redv[32]
// ---------------------------------------------------------------------------
#define SMEM_B_FLOATS (2048 + 2048 + 8192 + 32 + 32)
#define SMEM_B_BYTES  (SMEM_B_FLOATS * 4)

__device__ __forceinline__ float interp_li(float pos, const float* __restrict__ lir) {
    pos = fminf(pos, NPOS_M1);
    float pf = floorf(pos);
    int ip = (int)pf;
    float w = pos - pf;
    int ic = (ip < 63) ? ip + 1 : 63;
    float lf = lir[ip], lc = lir[ic];
    return fmaf(w, lc - lf, lf);
}

__global__ __launch_bounds__(256) void cope_kernel(
    const float* __restrict__ query, const float* __restrict__ key,
    const float* __restrict__ wk, float* __restrict__ out)
{
    extern __shared__ float sm[];
    float* qs    = sm;            // scaled q tile [32][64]
    float* li    = sm + 2048;     // logits_int tile [32][64]
    float* kpT   = sm + 4096;     // key_p chunk [64][128] (d-major)
    float* carry = kpT + 8192;    // [32]
    float* redv  = carry + 32;

    const int bh   = blockIdx.y;
    const int q0   = blockIdx.x * TQ;
    const int tid  = threadIdx.x;
    const int lane = tid & 31;
    const int cy   = tid >> 5;    // warp id: owns rows 4cy..4cy+3

    for (int idx = tid; idx < TQ * 16; idx += 256) {
        int r = idx >> 4, c = idx & 15;
        float4 v = ((const float4*)(query + ((size_t)bh * S + q0 + r) * D))[c];
        v.x *= 0.125f; v.y *= 0.125f; v.z *= 0.125f; v.w *= 0.125f;
        *(float4*)&qs[r * D + c * 4] = v;
        float4 L = ((const float4*)(g_lint + ((size_t)bh * S + q0 + r) * NPOS))[c];
        *(float4*)&li[r * NPOS + c * 4] = L;
    }
    if (tid < TQ) carry[tid] = 0.f;
    __syncthreads();

    const int cx = lane;          // lane owns cols 4cx..4cx+3 of the chunk

    for (int jc = S - KC; jc >= 0; jc -= KC) {
        // ---- stage key_p^T chunk ----
        if (jc >= KP_START) {
            for (int idx = tid; idx < D * (KC / 4); idx += 256) {
                int d = idx >> 5, c4 = idx & 31;
                float4 v = ((const float4*)(g_keypT + ((size_t)bh * D + d) * S + jc))[c4];
                *(float4*)&kpT[d * KC + c4 * 4] = v;
            }
        } else {
            // correctness fallback (never taken on typical data): on-the-fly keyproj
            for (int idx = tid; idx < D * KC; idx += 256) {
                int d = idx >> 7, c = idx & 127;
                const float* krow = key + ((size_t)bh * S + jc + c) * D;
                float s = 0.f;
#pragma unroll
                for (int k = 0; k < D; k++) s += krow[k] * wk[k * D + d];
                kpT[d * KC + c] = s;
            }
        }
        __syncthreads();

        // ---- 32x128x64 GEMM, packed f32x2, 4 rows x 4 cols per thread ----
        unsigned long long acc[4][2];
#pragma unroll
        for (int i = 0; i < 4; i++) { acc[i][0] = 0ull; acc[i][1] = 0ull; }

#pragma unroll
        for (int d4 = 0; d4 < 16; d4++) {
            float4 qv[4];
#pragma unroll
            for (int i = 0; i < 4; i++)          // warp-uniform (broadcast LDS)
                qv[i] = *(const float4*)&qs[(4 * cy + i) * D + 4 * d4];
#pragma unroll
            for (int t = 0; t < 4; t++) {
                ulonglong2 kv = *(const ulonglong2*)&kpT[(4 * d4 + t) * KC + 4 * cx];
#pragma unroll
                for (int i = 0; i < 4; i++) {
                    float a = (t == 0) ? qv[i].x : (t == 1) ? qv[i].y : (t == 2) ? qv[i].z : qv[i].w;
                    unsigned long long a2 = pack2(a);
                    fma2(acc[i][0], a2, kv.x);
                    fma2(acc[i][1], a2, kv.y);
                }
            }
        }

        // ---- sigmoid + register suffix-scan + interpolated store (per warp) ----
#pragma unroll
        for (int i = 0; i < 4; i++) {
            int r = 4 * cy + i;
            float2 u0 = unpack2(acc[i][0]), u1 = unpack2(acc[i][1]);
            float g0 = 1.f / (1.f + __expf(-u0.x));
            float g1 = 1.f / (1.f + __expf(-u0.y));
            float g2 = 1.f / (1.f + __expf(-u1.x));
            float g3 = 1.f / (1.f + __expf(-u1.y));
            // local suffix (col order: 4cx+0..4cx+3; suffix = toward larger col)
            float v3 = g3;
            float v2 = g2 + v3;
            float v1 = g1 + v2;
            float v0 = g0 + v1;
            float inc = v0;                       // lane total
#pragma unroll
            for (int off = 1; off < 32; off <<= 1) {
                float n = __shfl_down_sync(0xffffffffu, inc, off);
                if (lane + off < 32) inc += n;    // inclusive suffix over lanes
            }
            float excl = inc - v0;
            float c0 = carry[r];
            float base = c0 + excl;
            const float* lir = &li[r * NPOS];
            float4 o;
            o.x = interp_li(base + v0, lir);
            o.y = interp_li(base + v1, lir);
            o.z = interp_li(base + v2, lir);
            o.w = interp_li(base + v3, lir);
            *(float4*)(out + ((size_t)bh * S + q0 + r) * S + jc + 4 * cx) = o;
            if (lane == 0) carry[r] = c0 + inc;   // inc@lane0 = full chunk sum
        }
        __syncthreads();

        if (tid < 32) {
            float m = carry[tid];
#pragma unroll
            for (int off = 16; off; off >>= 1)
                m = fminf(m, __shfl_down_sync(0xffffffffu, m, off));
            if (tid == 0) redv[0] = m;
        }
        __syncthreads();

        if (redv[0] >= NPOS_M1) {
            if (jc > 0) {                         // remaining cols clamp to li[63]
                int nf4 = jc >> 2;
                for (int r = 0; r < TQ; r++) {
                    float Lv = li[r * NPOS + 63];
                    float4 o = make_float4(Lv, Lv, Lv, Lv);
                    float4* orow = (float4*)(out + ((size_t)bh * S + q0 + r) * S);
                    for (int c4 = tid; c4 < nf4; c4 += 256) orow[c4] = o;
                }
            }
            break;
        }
    }
}

// ---------------------------------------------------------------------------
extern "C" void kernel_launch(void* const* d_in, const int* in_sizes, int n_in,
                              void* d_out, int out_size) {
    const float* query = (const float*)d_in[0];
    const float* key   = (const float*)d_in[2];
    const float* pe    = (const float*)d_in[4];
    const float* wk    = (const float*)d_in[5];
    const int*   flag  = (const int*)d_in[6];
    float* out = (float*)d_out;

    // role y: 0..15 = lint s-chunks, 16..21 = keyproj tail s-chunks
    precompute_kernel<<<dim3(BH, 22), 256>>>(query, key, pe, wk, flag);

    cudaFuncSetAttribute(cope_kernel,
                         cudaFuncAttributeMaxDynamicSharedMemorySize, SMEM_B_BYTES);
    cope_kernel<<<dim3(S / TQ, BH), 256, SMEM_B_BYTES>>>(query, key, wk, out);
}

// round 3
// speedup vs baseline: 1.2667x; 1.0306x over previous
#include <cuda_runtime.h>
#include <cstdint>

#define S 1024
#define D 64
#define NPOS 64
#define BH 48
#define KC 128
#define TQ 64
#define KP_COLS 384            // precomputed keyproj tail columns
#define KP_START (S - KP_COLS) // 640
#define NPOS_M1 63.0f

// Scratch (allowed: __device__ globals)
__device__ float g_keypT[(size_t)BH * D * S];    // [bh][d][s] (only s >= KP_START filled)

// ---- packed f32x2 helpers ---------------------------------------------------
__device__ __forceinline__ unsigned long long pack2(float a) {
    unsigned long long r;
    asm("mov.b64 %0, {%1, %1};" : "=l"(r) : "f"(a));
    return r;
}
__device__ __forceinline__ void fma2(unsigned long long& d,
                                     unsigned long long a, unsigned long long b) {
    asm("fma.rn.f32x2 %0, %1, %2, %0;" : "+l"(d) : "l"(a), "l"(b));
}
__device__ __forceinline__ float2 unpack2(unsigned long long v) {
    float2 f;
    asm("mov.b64 {%0, %1}, %2;" : "=f"(f.x), "=f"(f.y) : "l"(v));
    return f;
}

// ---------------------------------------------------------------------------
// keyproj tail: g_keypT[bh][d][s] = sum_k key[bh][s][k]*w_k[k][d], s in tail 384
// ---------------------------------------------------------------------------
__global__ __launch_bounds__(256) void keyproj_kernel(
    const float* __restrict__ key, const float* __restrict__ wk)
{
    __shared__ float w_s[64 * 64];
    __shared__ float in_s[64 * 68];
    const int bh  = blockIdx.x;
    const int s0  = KP_START + blockIdx.y * 64;
    const int tid = threadIdx.x;

    for (int idx = tid; idx < 1024; idx += 256)
        ((float4*)w_s)[idx] = ((const float4*)wk)[idx];
    {
        const float* kp = key + ((size_t)bh * S + s0) * D;
        for (int idx = tid; idx < 64 * 16; idx += 256) {
            int r = idx >> 4, c = idx & 15;
            float4 v = ((const float4*)(kp + (size_t)r * D))[c];
            *(float4*)&in_s[r * 68 + c * 4] = v;
        }
    }
    __syncthreads();

    const int ox = tid & 15;   // d-group
    const int sy = tid >> 4;   // s-group

    unsigned long long acc[4][2];
#pragma unroll
    for (int i = 0; i < 4; i++) { acc[i][0] = 0ull; acc[i][1] = 0ull; }

#pragma unroll
    for (int k4 = 0; k4 < 16; k4++) {
        float4 av[4];
#pragma unroll
        for (int i = 0; i < 4; i++)
            av[i] = *(const float4*)&in_s[(4 * sy + i) * 68 + 4 * k4];
#pragma unroll
        for (int t = 0; t < 4; t++) {
            ulonglong2 wv = *(const ulonglong2*)&w_s[(4 * k4 + t) * 64 + 4 * ox];
#pragma unroll
            for (int i = 0; i < 4; i++) {
                float a = (t == 0) ? av[i].x : (t == 1) ? av[i].y : (t == 2) ? av[i].z : av[i].w;
                unsigned long long a2 = pack2(a);
                fma2(acc[i][0], a2, wv.x);
                fma2(acc[i][1], a2, wv.y);
            }
        }
    }

    float a_[4][4];
#pragma unroll
    for (int i = 0; i < 4; i++) {
        float2 u0 = unpack2(acc[i][0]), u1 = unpack2(acc[i][1]);
        a_[i][0] = u0.x; a_[i][1] = u0.y; a_[i][2] = u1.x; a_[i][3] = u1.y;
    }
#pragma unroll
    for (int j = 0; j < 4; j++) {
        float4 o = make_float4(a_[0][j], a_[1][j], a_[2][j], a_[3][j]);
        *(float4*)&g_keypT[((size_t)bh * D + 4 * ox + j) * S + s0 + 4 * sy] = o;
    }
}

// ---------------------------------------------------------------------------
// Main fused kernel.
// smem (floats): qs2 (dup f32x2, 8192) | li (4096) | kpT (8192) | wmin (16)
// Warp w owns rows 8w..8w+7; lane owns chunk cols 4*lane..4*lane+3.
// ---------------------------------------------------------------------------
#define QS2_OFF 0
#define LI_OFF  8192
#define KPT_OFF 12288
#define WMIN_OFF 20480
#define SMEM_FLOATS (20480 + 16)
#define SMEM_BYTES (SMEM_FLOATS * 4)

__device__ __forceinline__ float interp_li(float pos, const float* __restrict__ lir) {
    pos = fminf(pos, NPOS_M1);
    float pf = floorf(pos);
    int ip = (int)pf;
    float w = pos - pf;
    int ic = (ip < 63) ? ip + 1 : 63;
    float lf = lir[ip], lc = lir[ic];
    return fmaf(w, lc - lf, lf);
}

__global__ __launch_bounds__(256) void cope_kernel(
    const float* __restrict__ query, const float* __restrict__ key,
    const float* __restrict__ pe, const float* __restrict__ wk,
    const int* __restrict__ flag, float* __restrict__ out)
{
    extern __shared__ float sm[];
    unsigned long long* qs2u = (unsigned long long*)sm;   // [64][64] dup pairs
    float* li   = sm + LI_OFF;                            // [64][64]
    float* kpT  = sm + KPT_OFF;                           // [64][128]
    float* peS  = sm + KPT_OFF;                           // staged pe (pre-loop)
    float* liin = sm + KPT_OFF + 4096;                    // staged li input rows
    float* wminS = sm + WMIN_OFF;                         // [8]

    const int bh   = blockIdx.y;
    const int q0   = blockIdx.x * TQ;
    const int tid  = threadIdx.x;
    const int lane = tid & 31;
    const int wrp  = tid >> 5;

    // ---- stage: qs2 (query*0.125 dup), pe, liin -----------------------------
    const float* lisrc = (flag[0] != 0) ? query : key;
    for (int idx = tid; idx < TQ * 16; idx += 256) {
        int r = idx >> 4, c = idx & 15;
        float4 v = ((const float4*)(query + ((size_t)bh * S + q0 + r) * D))[c];
        ulonglong2 p0, p1;
        p0.x = pack2(v.x * 0.125f); p0.y = pack2(v.y * 0.125f);
        p1.x = pack2(v.z * 0.125f); p1.y = pack2(v.w * 0.125f);
        *(ulonglong2*)&qs2u[r * D + c * 4]     = p0;
        *(ulonglong2*)&qs2u[r * D + c * 4 + 2] = p1;
        float4 L = ((const float4*)(lisrc + ((size_t)bh * S + q0 + r) * D))[c];
        *(float4*)&liin[r * D + c * 4] = L;
    }
    for (int idx = tid; idx < 1024; idx += 256)
        ((float4*)peS)[idx] = ((const float4*)pe)[idx];
    __syncthreads();

    // ---- li tile: li[r][p] = sum_d liin[r][d] * pe[d][p] --------------------
    {
        const int ox = tid & 15;   // p-group (4 cols)
        const int sy = tid >> 4;   // row-group (4 rows)
        unsigned long long acc[4][2];
#pragma unroll
        for (int i = 0; i < 4; i++) { acc[i][0] = 0ull; acc[i][1] = 0ull; }
#pragma unroll
        for (int k4 = 0; k4 < 16; k4++) {
            float4 av[4];
#pragma unroll
            for (int i = 0; i < 4; i++)
                av[i] = *(const float4*)&liin[(4 * sy + i) * D + 4 * k4];
#pragma unroll
            for (int t = 0; t < 4; t++) {
                ulonglong2 wv = *(const ulonglong2*)&peS[(4 * k4 + t) * 64 + 4 * ox];
#pragma unroll
                for (int i = 0; i < 4; i++) {
                    float a = (t == 0) ? av[i].x : (t == 1) ? av[i].y : (t == 2) ? av[i].z : av[i].w;
                    unsigned long long a2 = pack2(a);
                    fma2(acc[i][0], a2, wv.x);
                    fma2(acc[i][1], a2, wv.y);
                }
            }
        }
#pragma unroll
        for (int i = 0; i < 4; i++) {
            float2 u0 = unpack2(acc[i][0]), u1 = unpack2(acc[i][1]);
            float4 o = make_float4(u0.x, u0.y, u1.x, u1.y);
            *(float4*)&li[(4 * sy + i) * NPOS + 4 * ox] = o;
        }
    }
    __syncthreads();   // li complete; kpT region free for staging

    // ---- main backward chunk loop -------------------------------------------
    float carry[8];
#pragma unroll
    for (int i = 0; i < 8; i++) carry[i] = 0.f;
    bool wdone = false;
    float wm = 0.f;

    for (int jc = S - KC; jc >= 0; jc -= KC) {
        // stage kpT chunk [64][128]
        if (jc >= KP_START) {
#pragma unroll
            for (int u = 0; u < 8; u++) {
                int idx = tid + u * 256;          // 2048 float4 total
                int d = idx >> 5, c4 = idx & 31;
                float4 v = ((const float4*)(g_keypT + ((size_t)bh * D + d) * S + jc))[c4];
                *(float4*)&kpT[d * KC + c4 * 4] = v;
            }
        } else {
            // correctness fallback (statistically never taken): on-the-fly keyproj
            for (int idx = tid; idx < D * KC; idx += 256) {
                int d = idx >> 7, c = idx & 127;
                const float* krow = key + ((size_t)bh * S + jc + c) * D;
                float s = 0.f;
#pragma unroll
                for (int k = 0; k < D; k++) s += krow[k] * wk[k * D + d];
                kpT[d * KC + c] = s;
            }
        }
        __syncthreads();

        if (!wdone) {
            // 64x128x64 GEMM slice: this warp's 8 rows, lane cols 4*lane..+3
            unsigned long long acc[8][2];
#pragma unroll
            for (int i = 0; i < 8; i++) { acc[i][0] = 0ull; acc[i][1] = 0ull; }

#pragma unroll
            for (int d4 = 0; d4 < 16; d4++) {
                ulonglong2 kv[4];
#pragma unroll
                for (int t = 0; t < 4; t++)
                    kv[t] = *(const ulonglong2*)&kpT[(4 * d4 + t) * KC + 4 * lane];
#pragma unroll
                for (int i = 0; i < 8; i++) {
                    const unsigned long long* qrow = qs2u + (8 * wrp + i) * D + 4 * d4;
                    ulonglong2 a01 = *(const ulonglong2*)qrow;
                    ulonglong2 a23 = *(const ulonglong2*)(qrow + 2);
                    fma2(acc[i][0], a01.x, kv[0].x); fma2(acc[i][1], a01.x, kv[0].y);
                    fma2(acc[i][0], a01.y, kv[1].x); fma2(acc[i][1], a01.y, kv[1].y);
                    fma2(acc[i][0], a23.x, kv[2].x); fma2(acc[i][1], a23.x, kv[2].y);
                    fma2(acc[i][0], a23.y, kv[3].x); fma2(acc[i][1], a23.y, kv[3].y);
                }
            }

            // sigmoid + suffix scan + interp store, per row
            wm = 1e30f;
#pragma unroll
            for (int i = 0; i < 8; i++) {
                int r = 8 * wrp + i;
                float2 u0 = unpack2(acc[i][0]), u1 = unpack2(acc[i][1]);
                float g0 = __fdividef(1.f, 1.f + __expf(-u0.x));
                float g1 = __fdividef(1.f, 1.f + __expf(-u0.y));
                float g2 = __fdividef(1.f, 1.f + __expf(-u1.x));
                float g3 = __fdividef(1.f, 1.f + __expf(-u1.y));
                float v3 = g3;
                float v2 = g2 + v3;
                float v1 = g1 + v2;
                float v0 = g0 + v1;
                float inc = v0;
#pragma unroll
                for (int off = 1; off < 32; off <<= 1) {
                    float n = __shfl_down_sync(0xffffffffu, inc, off);
                    if (lane + off < 32) inc += n;
                }
                float base = carry[i] + (inc - v0);
                const float* lir = &li[r * NPOS];
                float4 o;
                o.x = interp_li(base + v0, lir);
                o.y = interp_li(base + v1, lir);
                o.z = interp_li(base + v2, lir);
                o.w = interp_li(base + v3, lir);
                *(float4*)(out + ((size_t)bh * S + q0 + r) * S + jc + 4 * lane) = o;
                carry[i] += __shfl_sync(0xffffffffu, inc, 0);
                wm = fminf(wm, carry[i]);
            }

            if (wm >= NPOS_M1) {
                wdone = true;
                // fill remaining cols [0, jc) for this warp's rows
                int nf4 = jc >> 2;
#pragma unroll
                for (int i = 0; i < 8; i++) {
                    int r = 8 * wrp + i;
                    float Lv = li[r * NPOS + 63];
                    float4 o = make_float4(Lv, Lv, Lv, Lv);
                    float4* orow = (float4*)(out + ((size_t)bh * S + q0 + r) * S);
                    for (int c4 = lane; c4 < nf4; c4 += 32) orow[c4] = o;
                }
            }
        }

        if (lane == 0) wminS[wrp] = wdone ? 1e30f : wm;
        __syncthreads();

        float m = fminf(fminf(fminf(wminS[0], wminS[1]), fminf(wminS[2], wminS[3])),
                        fminf(fminf(wminS[4], wminS[5]), fminf(wminS[6], wminS[7])));
        if (m >= NPOS_M1) break;   // every warp done (or filled)
    }
}

// ---------------------------------------------------------------------------
extern "C" void kernel_launch(void* const* d_in, const int* in_sizes, int n_in,
                              void* d_out, int out_size) {
    const float* query = (const float*)d_in[0];
    const float* key   = (const float*)d_in[2];
    const float* pe    = (const float*)d_in[4];
    const float* wk    = (const float*)d_in[5];
    const int*   flag  = (const int*)d_in[6];
    float* out = (float*)d_out;

    keyproj_kernel<<<dim3(BH, KP_COLS / 64), 256>>>(key, wk);

    cudaFuncSetAttribute(cope_kernel,
                         cudaFuncAttributeMaxDynamicSharedMemorySize, SMEM_BYTES);
    cope_kernel<<<dim3(S / TQ, BH), 256, SMEM_BYTES>>>(query, key, pe, wk, flag, out);
}